// round 16
// baseline (speedup 1.0000x reference)
#include <cuda_runtime.h>

// ---------------- device scratch ----------------
__device__ float g_protR[16u*1024*1152];    // tf32-rounded prot
__device__ float g_W1R [1152*512];
__device__ float g_W2R [512*128];
__device__ float g_WoutR[256*128];
__device__ float g_Wh  [16u*4*512*64];      // [B,H,N,GAT] (tf32-rounded)
__device__ float g_s1  [16u*4*512];
__device__ float g_s2  [16u*4*512];
__device__ float g_att1[16u*4*512*512];     // [B,H,N,N] (tf32-rounded)
__device__ float g_multi[16u*512*256];      // (tf32-rounded)
__device__ float g_Wh2 [16u*512*128];       // (tf32-rounded)
__device__ float g_t1  [16u*512];
__device__ float g_t2  [16u*512];
__device__ float g_att2[16u*512*512];       // (tf32-rounded)
__device__ float g_hp2 [16u*512*128];
__device__ float g_hid [16u*1024*512];      // (tf32-rounded)

// ---------------- PTX helpers ----------------
__device__ __forceinline__ void cp16(float* s, const float* g) {
    unsigned sa = (unsigned)__cvta_generic_to_shared(s);
    asm volatile("cp.async.cg.shared.global [%0], [%1], 16;\n" :: "r"(sa), "l"(g));
}
__device__ __forceinline__ float rnd(float x) {
    unsigned u; asm("cvt.rna.tf32.f32 %0, %1;" : "=r"(u) : "f"(x));
    return __uint_as_float(u);
}
__device__ __forceinline__ void mma8(float* c, const unsigned* a, const unsigned* b) {
    asm volatile(
        "mma.sync.aligned.m16n8k8.row.col.f32.tf32.tf32.f32 "
        "{%0,%1,%2,%3},{%4,%5,%6,%7},{%8,%9},{%0,%1,%2,%3};"
        : "+f"(c[0]), "+f"(c[1]), "+f"(c[2]), "+f"(c[3])
        : "r"(a[0]), "r"(a[1]), "r"(a[2]), "r"(a[3]), "r"(b[0]), "r"(b[1]));
}

// ---------------- elementwise tf32 rounding ----------------
__global__ void k_round(const float* __restrict__ src, float* __restrict__ dst, int n4)
{
    int i = blockIdx.x * blockDim.x + threadIdx.x;
    int stride = gridDim.x * blockDim.x;
    for (; i < n4; i += stride) {
        float4 v = ((const float4*)src)[i];
        v.x = rnd(v.x); v.y = rnd(v.y); v.z = rnd(v.z); v.w = rnd(v.w);
        ((float4*)dst)[i] = v;
    }
}

// ---------------- K1: av = emb[atoms]; Wh = av @ W_gat; s1,s2 ----------------
__global__ void k_embed_gat1(const int* __restrict__ atoms,
                             const float* __restrict__ emb_atom,
                             const float* __restrict__ W_gat,
                             const float* __restrict__ a_gat)
{
    __shared__ float av[128];
    __shared__ float r1[8], r2[8];
    int row = blockIdx.x;
    int t   = threadIdx.x;           // 256
    if (t < 128) {
        int atom = atoms[row];
        av[t] = emb_atom[atom * 128 + t];
    }
    __syncthreads();
    int h = t >> 6, f = t & 63;
    const float* Wp = W_gat + (h * 128) * 64 + f;
    float acc = 0.f;
#pragma unroll 8
    for (int c = 0; c < 128; c++) acc += av[c] * Wp[c * 64];
    int b  = row >> 9;
    int n  = row & 511;
    int bh = b * 4 + h;
    g_Wh[((long)bh * 512 + n) * 64 + f] = rnd(acc);
    float p1 = acc * a_gat[h * 128 + f];
    float p2 = acc * a_gat[h * 128 + 64 + f];
#pragma unroll
    for (int o = 16; o; o >>= 1) {
        p1 += __shfl_xor_sync(~0u, p1, o);
        p2 += __shfl_xor_sync(~0u, p2, o);
    }
    int w = t >> 5;
    if ((t & 31) == 0) { r1[w] = p1; r2[w] = p2; }
    __syncthreads();
    if ((t & 63) == 0) {
        g_s1[(long)bh * 512 + n] = r1[2 * h] + r1[2 * h + 1];
        g_s2[(long)bh * 512 + n] = r2[2 * h] + r2[2 * h + 1];
    }
}

// ---------------- 4-head fused attention rows ----------------
__global__ void k_att_rows4(const float* __restrict__ s1,
                            const float* __restrict__ s2,
                            const int*   __restrict__ adj,
                            float* __restrict__ att)
{
    __shared__ float sred[32];
    __shared__ float sinv[4];
    int t  = threadIdx.x;            // 256
    int bn = blockIdx.x;
    int n  = bn & 511;
    int b  = bn >> 9;
    const int* ar = adj + (long)bn * 512;
    int a0 = ar[t], a1 = ar[t + 256];

    float p0[4], p1[4];
#pragma unroll
    for (int h = 0; h < 4; h++) {
        int bh = b * 4 + h;
        float s1v = s1[bh * 512 + n];
        const float* s2r = s2 + bh * 512;
        float x0 = s1v + s2r[t];
        float x1 = s1v + s2r[t + 256];
        x0 = x0 > 0.f ? x0 : 0.2f * x0;
        x1 = x1 > 0.f ? x1 : 0.2f * x1;
        p0[h] = (a0 > 0) ? __expf(x0) : 0.f;
        p1[h] = (a1 > 0) ? __expf(x1) : 0.f;
        float sum = p0[h] + p1[h];
#pragma unroll
        for (int o = 16; o; o >>= 1) sum += __shfl_xor_sync(~0u, sum, o);
        if ((t & 31) == 0) sred[h * 8 + (t >> 5)] = sum;
    }
    __syncthreads();
    if (t < 32) {
        float v = sred[t];
        v += __shfl_xor_sync(~0u, v, 4);
        v += __shfl_xor_sync(~0u, v, 2);
        v += __shfl_xor_sync(~0u, v, 1);
        if ((t & 7) == 0) sinv[t >> 3] = 1.f / v;
    }
    __syncthreads();
#pragma unroll
    for (int h = 0; h < 4; h++) {
        float inv = sinv[h];
        float* arow = att + ((long)(b * 4 + h) * 512 + n) * 512;
        arow[t]       = rnd(p0[h] * inv);
        arow[t + 256] = rnd(p1[h] * inv);
    }
}

// ---------------- single-head attention rows ----------------
__global__ void k_att_rows1(const float* __restrict__ s1,
                            const float* __restrict__ s2,
                            const int*   __restrict__ adj,
                            float* __restrict__ att)
{
    __shared__ float sred[8];
    __shared__ float sinv;
    int t  = threadIdx.x;            // 256
    int bn = blockIdx.x;
    const int* ar = adj + (long)bn * 512;
    float s1v = s1[bn];
    const float* s2r = s2 + (bn >> 9) * 512;
    float x0 = s1v + s2r[t];
    float x1 = s1v + s2r[t + 256];
    x0 = x0 > 0.f ? x0 : 0.2f * x0;
    x1 = x1 > 0.f ? x1 : 0.2f * x1;
    float p0 = (ar[t] > 0) ? __expf(x0) : 0.f;
    float p1 = (ar[t + 256] > 0) ? __expf(x1) : 0.f;
    float sum = p0 + p1;
#pragma unroll
    for (int o = 16; o; o >>= 1) sum += __shfl_xor_sync(~0u, sum, o);
    if ((t & 31) == 0) sred[t >> 5] = sum;
    __syncthreads();
    if (t < 8) {
        float v = sred[t];
#pragma unroll
        for (int o = 4; o; o >>= 1) v += __shfl_xor_sync(0xffu, v, o);
        if (t == 0) sinv = 1.f / v;
    }
    __syncthreads();
    float inv = sinv;
    float* arow = att + (long)bn * 512;
    arow[t]       = rnd(p0 * inv);
    arow[t + 256] = rnd(p1 * inv);
}

// ---------------- tf32 tensor-core GEMM, multi-stage cp.async ----------------
// All operands pre-rounded tf32 bit-patterns; mainloop pure LDS+MMA.
// One barrier per K-iter (see r13 note).
// MODE 0: batched plain      C[bz*M*Nn + m*Nn + n]
// MODE 1: relu(x+bias[n]), rnd   C[m*Nn+n]
// MODE 2: leaky(x+bias[n]), protein remap out[(b*1536+512+l)*128+n]  (fp32)
// MODE 3: elu(x), rnd, head layout C[(b*512+m)*256 + h*64 + n], bz=b*4+h
// MODE 4: plain, rnd         C[m*Nn+n]
template<int BM, int BN, int BK, int WM, int WN, int MODE, int STAGES>
__global__ void __launch_bounds__(32 * (BM / WM) * (BN / WN))
tf32gemm(const float* __restrict__ A, const float* __restrict__ B,
         const float* __restrict__ bias, float* __restrict__ C,
         int M, int Nn, int K, long sA, long sB)
{
    constexpr int WARPS_M = BM / WM;
    constexpr int WARPS_N = BN / WN;
    constexpr int WARPS   = WARPS_M * WARPS_N;
    constexpr int THREADS = 32 * WARPS;
    static_assert(WARPS == 4 || WARPS == 8, "4 or 8 warps");
    constexpr int MT = WM / 16, NT = WN / 8;
    constexpr int AP = BK + 4;
    constexpr int BP = BN + 8;
    extern __shared__ float dyn[];
    float* Asm = dyn;
    float* Bsm = dyn + STAGES * BM * AP;

    int tid  = threadIdx.x;
    int lane = tid & 31, warp = tid >> 5;
    int wm = (warp % WARPS_M) * WM;
    int wn = (warp / WARPS_M) * WN;
    int gid = lane >> 2, tig = lane & 3;
    int bz = blockIdx.z;
    const float* Ab = A + (long)bz * sA + (long)(blockIdx.y * BM) * K;
    const float* Bb = B + (long)bz * sB + blockIdx.x * BN;

    float acc[MT][NT][4] = {};

    constexpr int A_F4 = BM * BK / 4;
    constexpr int B_F4 = BK * BN / 4;
    constexpr int A_IT = (A_F4 + THREADS - 1) / THREADS;
    constexpr int B_IT = (B_F4 + THREADS - 1) / THREADS;

    int KT = K / BK;
    auto load_stage = [&](int kt, int st) {
        float* As = Asm + st * BM * AP;
        float* Bs = Bsm + st * BK * BP;
        const float* Ag = Ab + kt * BK;
#pragma unroll
        for (int i = 0; i < A_IT; i++) {
            int c = tid + i * THREADS;
            if (A_F4 % THREADS == 0 || c < A_F4) {
                int r = c / (BK / 4), kc = c % (BK / 4);
                cp16(&As[r * AP + kc * 4], Ag + (long)r * K + kc * 4);
            }
        }
        const float* Bg = Bb + (long)(kt * BK) * Nn;
#pragma unroll
        for (int i = 0; i < B_IT; i++) {
            int c = tid + i * THREADS;
            if (B_F4 % THREADS == 0 || c < B_F4) {
                int r = c / (BN / 4), nc = c % (BN / 4);
                cp16(&Bs[r * BP + nc * 4], Bg + (long)r * Nn + nc * 4);
            }
        }
        asm volatile("cp.async.commit_group;\n" ::);
    };

#pragma unroll
    for (int s = 0; s < STAGES - 1; s++)
        if (s < KT) load_stage(s, s);

    for (int kt = 0; kt < KT; kt++) {
        int st = kt % STAGES;
        asm volatile("cp.async.wait_group %0;\n" :: "n"(STAGES - 2));
        __syncthreads();
        int pf = kt + STAGES - 1;
        if (pf < KT) load_stage(pf, pf % STAGES);

        float* As = Asm + st * BM * AP;
        float* Bs = Bsm + st * BK * BP;
#pragma unroll
        for (int k8 = 0; k8 < BK / 8; k8++) {
            int kb = k8 * 8;
            unsigned af[MT][4], bf[NT][2];
#pragma unroll
            for (int mt = 0; mt < MT; mt++) {
                int m0 = wm + mt * 16 + gid;
                af[mt][0] = __float_as_uint(As[m0 * AP + kb + tig]);
                af[mt][1] = __float_as_uint(As[(m0 + 8) * AP + kb + tig]);
                af[mt][2] = __float_as_uint(As[m0 * AP + kb + tig + 4]);
                af[mt][3] = __float_as_uint(As[(m0 + 8) * AP + kb + tig + 4]);
            }
#pragma unroll
            for (int nt = 0; nt < NT; nt++) {
                int n0 = wn + nt * 8 + gid;
                bf[nt][0] = __float_as_uint(Bs[(kb + tig) * BP + n0]);
                bf[nt][1] = __float_as_uint(Bs[(kb + tig + 4) * BP + n0]);
            }
#pragma unroll
            for (int mt = 0; mt < MT; mt++)
#pragma unroll
                for (int nt = 0; nt < NT; nt++)
                    mma8(acc[mt][nt], af[mt], bf[nt]);
        }
    }

#pragma unroll
    for (int mt = 0; mt < MT; mt++)
#pragma unroll
        for (int nt = 0; nt < NT; nt++)
#pragma unroll
            for (int h2 = 0; h2 < 2; h2++) {
                int m = blockIdx.y * BM + wm + mt * 16 + gid + h2 * 8;
                int n = blockIdx.x * BN + wn + nt * 8 + tig * 2;
                float v0 = acc[mt][nt][2 * h2];
                float v1 = acc[mt][nt][2 * h2 + 1];
                if (MODE == 0) {
                    long base = (long)bz * M * Nn + (long)m * Nn + n;
                    C[base] = v0; C[base + 1] = v1;
                } else if (MODE == 1) {
                    v0 = fmaxf(v0 + bias[n], 0.f);
                    v1 = fmaxf(v1 + bias[n + 1], 0.f);
                    long base = (long)m * Nn + n;
                    C[base] = rnd(v0); C[base + 1] = rnd(v1);
                } else if (MODE == 2) {
                    v0 += bias[n]; v1 += bias[n + 1];
                    v0 = (v0 >= 0.f) ? v0 : 0.2f * v0;
                    v1 = (v1 >= 0.f) ? v1 : 0.2f * v1;
                    int bb = m >> 10, l = m & 1023;
                    long base = ((long)(bb * 1536 + 512 + l)) * 128 + n;
                    C[base] = v0; C[base + 1] = v1;
                } else if (MODE == 3) {
                    v0 = (v0 > 0.f) ? v0 : (__expf(v0) - 1.f);
                    v1 = (v1 > 0.f) ? v1 : (__expf(v1) - 1.f);
                    int bb = bz >> 2, h = bz & 3;
                    long base = ((long)(bb * 512) + m) * 256 + h * 64 + n;
                    C[base] = rnd(v0); C[base + 1] = rnd(v1);
                } else {
                    long base = (long)m * Nn + n;
                    C[base] = rnd(v0); C[base + 1] = rnd(v1);
                }
            }
}

// ---------------- t1,t2 from Wh2 ----------------
__global__ void k_t12(const float* __restrict__ a_out)
{
    __shared__ float r1[4], r2[4];
    int row = blockIdx.x;
    int t   = threadIdx.x;           // 128
    float v  = g_Wh2[(long)row * 128 + t];
    float p1 = v * a_out[t];
    float p2 = v * a_out[128 + t];
#pragma unroll
    for (int o = 16; o; o >>= 1) {
        p1 += __shfl_xor_sync(~0u, p1, o);
        p2 += __shfl_xor_sync(~0u, p2, o);
    }
    int w = t >> 5;
    if ((t & 31) == 0) { r1[w] = p1; r2[w] = p2; }
    __syncthreads();
    if (t == 0) {
        g_t1[row] = r1[0] + r1[1] + r1[2] + r1[3];
        g_t2[row] = r2[0] + r2[1] + r2[2] + r2[3];
    }
}

// ---------------- final: out_atoms = leaky(elu(hp2) @ Wc + bc) ----------------
__global__ void k_final_atoms(const float* __restrict__ Wc,
                              const float* __restrict__ bc,
                              float* __restrict__ out)
{
    __shared__ float x[128];
    int row = blockIdx.x;
    int t   = threadIdx.x;           // 128
    float v = g_hp2[(long)row * 128 + t];
    x[t] = (v > 0.f) ? v : (__expf(v) - 1.f);
    __syncthreads();
    float acc = bc[t];
#pragma unroll 8
    for (int c = 0; c < 128; c++) acc += x[c] * Wc[c * 128 + t];
    acc = (acc >= 0.f) ? acc : 0.2f * acc;
    int b = row >> 9;
    out[((long)row + b * 1024) * 128 + t] = acc;
}

// ---------------- launch ----------------
static inline int gemm_smem(int BM, int BN, int BK, int ST) {
    return ST * (BM * (BK + 4) + BK * (BN + 8)) * (int)sizeof(float);
}

extern "C" void kernel_launch(void* const* d_in, const int* in_sizes, int n_in,
                              void* d_out, int out_size)
{
    const int*   atoms    = (const int*)  d_in[0];
    const int*   adj      = (const int*)  d_in[1];
    const float* prot     = (const float*)d_in[3];
    const float* emb_atom = (const float*)d_in[5];
    const float* W_gat    = (const float*)d_in[6];
    const float* a_gat    = (const float*)d_in[7];
    const float* W_out    = (const float*)d_in[8];
    const float* a_out    = (const float*)d_in[9];
    const float* Wc       = (const float*)d_in[10];
    const float* bc       = (const float*)d_in[11];
    const float* W1       = (const float*)d_in[12];
    const float* b1       = (const float*)d_in[13];
    const float* W2       = (const float*)d_in[14];
    const float* b2       = (const float*)d_in[15];
    float* out = (float*)d_out;

    void *pProtR, *pW1R, *pW2R, *pWoutR;
    void *pWh, *pS1, *pS2, *pAtt1, *pMulti, *pWh2, *pT1, *pT2, *pAtt2, *pHp2, *pHid;
    cudaGetSymbolAddress(&pProtR, g_protR);
    cudaGetSymbolAddress(&pW1R,  g_W1R);
    cudaGetSymbolAddress(&pW2R,  g_W2R);
    cudaGetSymbolAddress(&pWoutR,g_WoutR);
    cudaGetSymbolAddress(&pWh,   g_Wh);
    cudaGetSymbolAddress(&pS1,   g_s1);
    cudaGetSymbolAddress(&pS2,   g_s2);
    cudaGetSymbolAddress(&pAtt1, g_att1);
    cudaGetSymbolAddress(&pMulti,g_multi);
    cudaGetSymbolAddress(&pWh2,  g_Wh2);
    cudaGetSymbolAddress(&pT1,   g_t1);
    cudaGetSymbolAddress(&pT2,   g_t2);
    cudaGetSymbolAddress(&pAtt2, g_att2);
    cudaGetSymbolAddress(&pHp2,  g_hp2);
    cudaGetSymbolAddress(&pHid,  g_hid);

    static cudaStream_t sB = nullptr, sC = nullptr;
    static cudaEvent_t evFork = nullptr, evJoin = nullptr, e0 = nullptr, e1 = nullptr;
    if (!sB) {
        cudaStreamCreateWithFlags(&sB, cudaStreamNonBlocking);
        cudaStreamCreateWithFlags(&sC, cudaStreamNonBlocking);
        cudaEventCreateWithFlags(&evFork, cudaEventDisableTiming);
        cudaEventCreateWithFlags(&evJoin, cudaEventDisableTiming);
        cudaEventCreateWithFlags(&e0, cudaEventDisableTiming);
        cudaEventCreateWithFlags(&e1, cudaEventDisableTiming);
        cudaFuncSetAttribute(tf32gemm<256,128,16,64,64,1,3>,
                             cudaFuncAttributeMaxDynamicSharedMemorySize,
                             gemm_smem(256,128,16,3));
        cudaFuncSetAttribute(tf32gemm<32,128,16,16,32,2,3>,
                             cudaFuncAttributeMaxDynamicSharedMemorySize,
                             gemm_smem(32,128,16,3));
        cudaFuncSetAttribute(tf32gemm<128,64,16,64,16,3,3>,
                             cudaFuncAttributeMaxDynamicSharedMemorySize,
                             gemm_smem(128,64,16,3));
        cudaFuncSetAttribute(tf32gemm<64,128,16,32,32,4,3>,
                             cudaFuncAttributeMaxDynamicSharedMemorySize,
                             gemm_smem(64,128,16,3));
        cudaFuncSetAttribute(tf32gemm<64,128,16,32,32,0,3>,
                             cudaFuncAttributeMaxDynamicSharedMemorySize,
                             gemm_smem(64,128,16,3));
    }

    const long PROT_HALF = 16L * 1024 * 1152 / 2;    // elements per half

    // ---- fork ----
    cudaEventRecord(evFork, 0);
    cudaStreamWaitEvent(sB, evFork, 0);
    cudaStreamWaitEvent(sC, evFork, 0);

    // stream B: prot rounding in two halves
    k_round<<<1024, 256, 0, sB>>>(prot, (float*)pProtR, (int)(PROT_HALF / 4));
    cudaEventRecord(e0, sB);
    k_round<<<1024, 256, 0, sB>>>(prot + PROT_HALF, (float*)pProtR + PROT_HALF,
                                  (int)(PROT_HALF / 4));
    cudaEventRecord(e1, sB);

    // stream C: FC chain (FC1 in two half-M launches, 256x128 blocks, 8 warps)
    k_round<<<148, 256, 0, sC>>>(W1, (float*)pW1R, 1152 * 512 / 4);
    cudaStreamWaitEvent(sC, e0, 0);
    tf32gemm<256,128,16,64,64,1,3><<<dim3(4,32,1), 256, gemm_smem(256,128,16,3), sC>>>(
        (const float*)pProtR, (const float*)pW1R, b1, (float*)pHid,
        16384, 512, 1152, 0, 0);
    cudaStreamWaitEvent(sC, e1, 0);
    tf32gemm<256,128,16,64,64,1,3><<<dim3(4,32,1), 256, gemm_smem(256,128,16,3), sC>>>(
        (const float*)pProtR + PROT_HALF, (const float*)pW1R, b1,
        (float*)pHid + 8192L * 512, 16384, 512, 1152, 0, 0);
    k_round<<<32, 256, 0, sC>>>(W2, (float*)pW2R, 512 * 128 / 4);
    // out_prot = leaky(hid @ W2 + b2)  [16384 x 128 x 512], row remap
    tf32gemm<32,128,16,16,32,2,3><<<dim3(1,512,1), 256, gemm_smem(32,128,16,3), sC>>>(
        (const float*)pHid, (const float*)pW2R, b2, out, 16384, 128, 512, 0, 0);
    cudaEventRecord(evJoin, sC);

    // ---- GAT chain on origin stream ----
    k_embed_gat1<<<16 * 512, 256>>>(atoms, emb_atom, W_gat, a_gat);
    k_round<<<16, 256>>>(W_out, (float*)pWoutR, 256 * 128 / 4);
    k_att_rows4<<<16 * 512, 256>>>((const float*)pS1, (const float*)pS2,
                                   adj, (float*)pAtt1);
    // multi = elu(att1 @ Wh)   [512 x 64 x 512] x 64 batches
    tf32gemm<128,64,16,64,16,3,3><<<dim3(1,4,64), 256, gemm_smem(128,64,16,3)>>>(
        (const float*)pAtt1, (const float*)pWh, nullptr, (float*)pMulti,
        512, 64, 512, (long)512 * 512, (long)512 * 64);
    // Wh2 = multi @ W_out   [8192 x 128 x 256]
    tf32gemm<64,128,16,32,32,4,3><<<dim3(1,128,1), 256, gemm_smem(64,128,16,3)>>>(
        (const float*)pMulti, (const float*)pWoutR, nullptr, (float*)pWh2,
        8192, 128, 256, 0, 0);
    k_t12<<<16 * 512, 128>>>(a_out);
    k_att_rows1<<<16 * 512, 256>>>((const float*)pT1, (const float*)pT2,
                                   adj, (float*)pAtt2);
    // hp2 = att2 @ Wh2   [512 x 128 x 512] x 16 batches
    tf32gemm<64,128,16,32,32,0,3><<<dim3(1,8,16), 256, gemm_smem(64,128,16,3)>>>(
        (const float*)pAtt2, (const float*)pWh2, nullptr, (float*)pHp2,
        512, 128, 512, (long)512 * 512, (long)512 * 128);
    k_final_atoms<<<16 * 512, 128>>>(Wc, bc, out);

    // ---- join ----
    cudaStreamWaitEvent(0, evJoin, 0);
}

// round 17
// speedup vs baseline: 1.6328x; 1.6328x over previous
#include <cuda_runtime.h>

// ---------------- device scratch ----------------
__device__ float g_protR[16u*1024*1152];    // tf32-rounded prot
__device__ float g_W1R [1152*512];
__device__ float g_W2R [512*128];
__device__ float g_WoutR[256*128];
__device__ float g_Wh  [16u*4*512*64];      // [B,H,N,GAT] (tf32-rounded)
__device__ float g_s1  [16u*4*512];
__device__ float g_s2  [16u*4*512];
__device__ float g_att1[16u*4*512*512];     // [B,H,N,N] (tf32-rounded)
__device__ float g_multi[16u*512*256];      // (tf32-rounded)
__device__ float g_Wh2 [16u*512*128];       // (tf32-rounded)
__device__ float g_t1  [16u*512];
__device__ float g_t2  [16u*512];
__device__ float g_att2[16u*512*512];       // (tf32-rounded)
__device__ float g_hp2 [16u*512*128];
__device__ float g_hid [16u*1024*512];      // (tf32-rounded)

// ---------------- PTX helpers ----------------
__device__ __forceinline__ void cp16(float* s, const float* g) {
    unsigned sa = (unsigned)__cvta_generic_to_shared(s);
    asm volatile("cp.async.cg.shared.global [%0], [%1], 16;\n" :: "r"(sa), "l"(g));
}
__device__ __forceinline__ float rnd(float x) {
    unsigned u; asm("cvt.rna.tf32.f32 %0, %1;" : "=r"(u) : "f"(x));
    return __uint_as_float(u);
}
__device__ __forceinline__ void mma8(float* c, const unsigned* a, const unsigned* b) {
    asm volatile(
        "mma.sync.aligned.m16n8k8.row.col.f32.tf32.tf32.f32 "
        "{%0,%1,%2,%3},{%4,%5,%6,%7},{%8,%9},{%0,%1,%2,%3};"
        : "+f"(c[0]), "+f"(c[1]), "+f"(c[2]), "+f"(c[3])
        : "r"(a[0]), "r"(a[1]), "r"(a[2]), "r"(a[3]), "r"(b[0]), "r"(b[1]));
}

// ---------------- elementwise tf32 rounding ----------------
__global__ void k_round(const float* __restrict__ src, float* __restrict__ dst, int n4)
{
    int i = blockIdx.x * blockDim.x + threadIdx.x;
    int stride = gridDim.x * blockDim.x;
    for (; i < n4; i += stride) {
        float4 v = ((const float4*)src)[i];
        v.x = rnd(v.x); v.y = rnd(v.y); v.z = rnd(v.z); v.w = rnd(v.w);
        ((float4*)dst)[i] = v;
    }
}

// ---------------- K1: av = emb[atoms]; Wh = av @ W_gat; s1,s2 ----------------
__global__ void k_embed_gat1(const int* __restrict__ atoms,
                             const float* __restrict__ emb_atom,
                             const float* __restrict__ W_gat,
                             const float* __restrict__ a_gat)
{
    __shared__ float av[128];
    __shared__ float r1[8], r2[8];
    int row = blockIdx.x;
    int t   = threadIdx.x;           // 256
    if (t < 128) {
        int atom = atoms[row];
        av[t] = emb_atom[atom * 128 + t];
    }
    __syncthreads();
    int h = t >> 6, f = t & 63;
    const float* Wp = W_gat + (h * 128) * 64 + f;
    float acc = 0.f;
#pragma unroll 8
    for (int c = 0; c < 128; c++) acc += av[c] * Wp[c * 64];
    int b  = row >> 9;
    int n  = row & 511;
    int bh = b * 4 + h;
    g_Wh[((long)bh * 512 + n) * 64 + f] = rnd(acc);
    float p1 = acc * a_gat[h * 128 + f];
    float p2 = acc * a_gat[h * 128 + 64 + f];
#pragma unroll
    for (int o = 16; o; o >>= 1) {
        p1 += __shfl_xor_sync(~0u, p1, o);
        p2 += __shfl_xor_sync(~0u, p2, o);
    }
    int w = t >> 5;
    if ((t & 31) == 0) { r1[w] = p1; r2[w] = p2; }
    __syncthreads();
    if ((t & 63) == 0) {
        g_s1[(long)bh * 512 + n] = r1[2 * h] + r1[2 * h + 1];
        g_s2[(long)bh * 512 + n] = r2[2 * h] + r2[2 * h + 1];
    }
}

// ---------------- 4-head fused attention rows ----------------
__global__ void k_att_rows4(const float* __restrict__ s1,
                            const float* __restrict__ s2,
                            const int*   __restrict__ adj,
                            float* __restrict__ att)
{
    __shared__ float sred[32];
    __shared__ float sinv[4];
    int t  = threadIdx.x;            // 256
    int bn = blockIdx.x;
    int n  = bn & 511;
    int b  = bn >> 9;
    const int* ar = adj + (long)bn * 512;
    int a0 = ar[t], a1 = ar[t + 256];

    float p0[4], p1[4];
#pragma unroll
    for (int h = 0; h < 4; h++) {
        int bh = b * 4 + h;
        float s1v = s1[bh * 512 + n];
        const float* s2r = s2 + bh * 512;
        float x0 = s1v + s2r[t];
        float x1 = s1v + s2r[t + 256];
        x0 = x0 > 0.f ? x0 : 0.2f * x0;
        x1 = x1 > 0.f ? x1 : 0.2f * x1;
        p0[h] = (a0 > 0) ? __expf(x0) : 0.f;
        p1[h] = (a1 > 0) ? __expf(x1) : 0.f;
        float sum = p0[h] + p1[h];
#pragma unroll
        for (int o = 16; o; o >>= 1) sum += __shfl_xor_sync(~0u, sum, o);
        if ((t & 31) == 0) sred[h * 8 + (t >> 5)] = sum;
    }
    __syncthreads();
    if (t < 32) {
        float v = sred[t];
        v += __shfl_xor_sync(~0u, v, 4);
        v += __shfl_xor_sync(~0u, v, 2);
        v += __shfl_xor_sync(~0u, v, 1);
        if ((t & 7) == 0) sinv[t >> 3] = 1.f / v;
    }
    __syncthreads();
#pragma unroll
    for (int h = 0; h < 4; h++) {
        float inv = sinv[h];
        float* arow = att + ((long)(b * 4 + h) * 512 + n) * 512;
        arow[t]       = rnd(p0[h] * inv);
        arow[t + 256] = rnd(p1[h] * inv);
    }
}

// ---------------- single-head attention rows ----------------
__global__ void k_att_rows1(const float* __restrict__ s1,
                            const float* __restrict__ s2,
                            const int*   __restrict__ adj,
                            float* __restrict__ att)
{
    __shared__ float sred[8];
    __shared__ float sinv;
    int t  = threadIdx.x;            // 256
    int bn = blockIdx.x;
    const int* ar = adj + (long)bn * 512;
    float s1v = s1[bn];
    const float* s2r = s2 + (bn >> 9) * 512;
    float x0 = s1v + s2r[t];
    float x1 = s1v + s2r[t + 256];
    x0 = x0 > 0.f ? x0 : 0.2f * x0;
    x1 = x1 > 0.f ? x1 : 0.2f * x1;
    float p0 = (ar[t] > 0) ? __expf(x0) : 0.f;
    float p1 = (ar[t + 256] > 0) ? __expf(x1) : 0.f;
    float sum = p0 + p1;
#pragma unroll
    for (int o = 16; o; o >>= 1) sum += __shfl_xor_sync(~0u, sum, o);
    if ((t & 31) == 0) sred[t >> 5] = sum;
    __syncthreads();
    if (t < 8) {
        float v = sred[t];
#pragma unroll
        for (int o = 4; o; o >>= 1) v += __shfl_xor_sync(0xffu, v, o);
        if (t == 0) sinv = 1.f / v;
    }
    __syncthreads();
    float inv = sinv;
    float* arow = att + (long)bn * 512;
    arow[t]       = rnd(p0 * inv);
    arow[t + 256] = rnd(p1 * inv);
}

// ---------------- tf32 tensor-core GEMM, multi-stage cp.async ----------------
// All operands pre-rounded tf32 bit-patterns; mainloop pure LDS+MMA.
// One barrier per K-iter (see r13 note).
// MODE 0: batched plain      C[bz*M*Nn + m*Nn + n]
// MODE 1: relu(x+bias[n]), rnd   C[m*Nn+n]
// MODE 2: leaky(x+bias[n]), protein remap out[(b*1536+512+l)*128+n]  (fp32)
// MODE 3: elu(x), rnd, head layout C[(b*512+m)*256 + h*64 + n], bz=b*4+h
// MODE 4: plain, rnd         C[m*Nn+n]
template<int BM, int BN, int BK, int WM, int WN, int MODE, int STAGES>
__global__ void __launch_bounds__(32 * (BM / WM) * (BN / WN))
tf32gemm(const float* __restrict__ A, const float* __restrict__ B,
         const float* __restrict__ bias, float* __restrict__ C,
         int M, int Nn, int K, long sA, long sB)
{
    constexpr int WARPS_M = BM / WM;
    constexpr int WARPS_N = BN / WN;
    constexpr int WARPS   = WARPS_M * WARPS_N;
    constexpr int THREADS = 32 * WARPS;
    static_assert(WARPS == 4 || WARPS == 8, "4 or 8 warps");
    constexpr int MT = WM / 16, NT = WN / 8;
    constexpr int AP = BK + 4;
    constexpr int BP = BN + 8;
    extern __shared__ float dyn[];
    float* Asm = dyn;
    float* Bsm = dyn + STAGES * BM * AP;

    int tid  = threadIdx.x;
    int lane = tid & 31, warp = tid >> 5;
    int wm = (warp % WARPS_M) * WM;
    int wn = (warp / WARPS_M) * WN;
    int gid = lane >> 2, tig = lane & 3;
    int bz = blockIdx.z;
    const float* Ab = A + (long)bz * sA + (long)(blockIdx.y * BM) * K;
    const float* Bb = B + (long)bz * sB + blockIdx.x * BN;

    float acc[MT][NT][4] = {};

    constexpr int A_F4 = BM * BK / 4;
    constexpr int B_F4 = BK * BN / 4;
    constexpr int A_IT = (A_F4 + THREADS - 1) / THREADS;
    constexpr int B_IT = (B_F4 + THREADS - 1) / THREADS;

    int KT = K / BK;
    auto load_stage = [&](int kt, int st) {
        float* As = Asm + st * BM * AP;
        float* Bs = Bsm + st * BK * BP;
        const float* Ag = Ab + kt * BK;
#pragma unroll
        for (int i = 0; i < A_IT; i++) {
            int c = tid + i * THREADS;
            if (A_F4 % THREADS == 0 || c < A_F4) {
                int r = c / (BK / 4), kc = c % (BK / 4);
                cp16(&As[r * AP + kc * 4], Ag + (long)r * K + kc * 4);
            }
        }
        const float* Bg = Bb + (long)(kt * BK) * Nn;
#pragma unroll
        for (int i = 0; i < B_IT; i++) {
            int c = tid + i * THREADS;
            if (B_F4 % THREADS == 0 || c < B_F4) {
                int r = c / (BN / 4), nc = c % (BN / 4);
                cp16(&Bs[r * BP + nc * 4], Bg + (long)r * Nn + nc * 4);
            }
        }
        asm volatile("cp.async.commit_group;\n" ::);
    };

#pragma unroll
    for (int s = 0; s < STAGES - 1; s++)
        if (s < KT) load_stage(s, s);

    for (int kt = 0; kt < KT; kt++) {
        int st = kt % STAGES;
        asm volatile("cp.async.wait_group %0;\n" :: "n"(STAGES - 2));
        __syncthreads();
        int pf = kt + STAGES - 1;
        if (pf < KT) load_stage(pf, pf % STAGES);

        float* As = Asm + st * BM * AP;
        float* Bs = Bsm + st * BK * BP;
#pragma unroll
        for (int k8 = 0; k8 < BK / 8; k8++) {
            int kb = k8 * 8;
            unsigned af[MT][4], bf[NT][2];
#pragma unroll
            for (int mt = 0; mt < MT; mt++) {
                int m0 = wm + mt * 16 + gid;
                af[mt][0] = __float_as_uint(As[m0 * AP + kb + tig]);
                af[mt][1] = __float_as_uint(As[(m0 + 8) * AP + kb + tig]);
                af[mt][2] = __float_as_uint(As[m0 * AP + kb + tig + 4]);
                af[mt][3] = __float_as_uint(As[(m0 + 8) * AP + kb + tig + 4]);
            }
#pragma unroll
            for (int nt = 0; nt < NT; nt++) {
                int n0 = wn + nt * 8 + gid;
                bf[nt][0] = __float_as_uint(Bs[(kb + tig) * BP + n0]);
                bf[nt][1] = __float_as_uint(Bs[(kb + tig + 4) * BP + n0]);
            }
#pragma unroll
            for (int mt = 0; mt < MT; mt++)
#pragma unroll
                for (int nt = 0; nt < NT; nt++)
                    mma8(acc[mt][nt], af[mt], bf[nt]);
        }
    }

#pragma unroll
    for (int mt = 0; mt < MT; mt++)
#pragma unroll
        for (int nt = 0; nt < NT; nt++)
#pragma unroll
            for (int h2 = 0; h2 < 2; h2++) {
                int m = blockIdx.y * BM + wm + mt * 16 + gid + h2 * 8;
                int n = blockIdx.x * BN + wn + nt * 8 + tig * 2;
                float v0 = acc[mt][nt][2 * h2];
                float v1 = acc[mt][nt][2 * h2 + 1];
                if (MODE == 0) {
                    long base = (long)bz * M * Nn + (long)m * Nn + n;
                    C[base] = v0; C[base + 1] = v1;
                } else if (MODE == 1) {
                    v0 = fmaxf(v0 + bias[n], 0.f);
                    v1 = fmaxf(v1 + bias[n + 1], 0.f);
                    long base = (long)m * Nn + n;
                    C[base] = rnd(v0); C[base + 1] = rnd(v1);
                } else if (MODE == 2) {
                    v0 += bias[n]; v1 += bias[n + 1];
                    v0 = (v0 >= 0.f) ? v0 : 0.2f * v0;
                    v1 = (v1 >= 0.f) ? v1 : 0.2f * v1;
                    int bb = m >> 10, l = m & 1023;
                    long base = ((long)(bb * 1536 + 512 + l)) * 128 + n;
                    C[base] = v0; C[base + 1] = v1;
                } else if (MODE == 3) {
                    v0 = (v0 > 0.f) ? v0 : (__expf(v0) - 1.f);
                    v1 = (v1 > 0.f) ? v1 : (__expf(v1) - 1.f);
                    int bb = bz >> 2, h = bz & 3;
                    long base = ((long)(bb * 512) + m) * 256 + h * 64 + n;
                    C[base] = rnd(v0); C[base + 1] = rnd(v1);
                } else {
                    long base = (long)m * Nn + n;
                    C[base] = rnd(v0); C[base + 1] = rnd(v1);
                }
            }
}

// ---------------- t1,t2 from Wh2 ----------------
__global__ void k_t12(const float* __restrict__ a_out)
{
    __shared__ float r1[4], r2[4];
    int row = blockIdx.x;
    int t   = threadIdx.x;           // 128
    float v  = g_Wh2[(long)row * 128 + t];
    float p1 = v * a_out[t];
    float p2 = v * a_out[128 + t];
#pragma unroll
    for (int o = 16; o; o >>= 1) {
        p1 += __shfl_xor_sync(~0u, p1, o);
        p2 += __shfl_xor_sync(~0u, p2, o);
    }
    int w = t >> 5;
    if ((t & 31) == 0) { r1[w] = p1; r2[w] = p2; }
    __syncthreads();
    if (t == 0) {
        g_t1[row] = r1[0] + r1[1] + r1[2] + r1[3];
        g_t2[row] = r2[0] + r2[1] + r2[2] + r2[3];
    }
}

// ---------------- final: out_atoms = leaky(elu(hp2) @ Wc + bc) ----------------
__global__ void k_final_atoms(const float* __restrict__ Wc,
                              const float* __restrict__ bc,
                              float* __restrict__ out)
{
    __shared__ float x[128];
    int row = blockIdx.x;
    int t   = threadIdx.x;           // 128
    float v = g_hp2[(long)row * 128 + t];
    x[t] = (v > 0.f) ? v : (__expf(v) - 1.f);
    __syncthreads();
    float acc = bc[t];
#pragma unroll 8
    for (int c = 0; c < 128; c++) acc += x[c] * Wc[c * 128 + t];
    acc = (acc >= 0.f) ? acc : 0.2f * acc;
    int b = row >> 9;
    out[((long)row + b * 1024) * 128 + t] = acc;
}

// ---------------- launch ----------------
static inline int gemm_smem(int BM, int BN, int BK, int ST) {
    return ST * (BM * (BK + 4) + BK * (BN + 8)) * (int)sizeof(float);
}

extern "C" void kernel_launch(void* const* d_in, const int* in_sizes, int n_in,
                              void* d_out, int out_size)
{
    const int*   atoms    = (const int*)  d_in[0];
    const int*   adj      = (const int*)  d_in[1];
    const float* prot     = (const float*)d_in[3];
    const float* emb_atom = (const float*)d_in[5];
    const float* W_gat    = (const float*)d_in[6];
    const float* a_gat    = (const float*)d_in[7];
    const float* W_out    = (const float*)d_in[8];
    const float* a_out    = (const float*)d_in[9];
    const float* Wc       = (const float*)d_in[10];
    const float* bc       = (const float*)d_in[11];
    const float* W1       = (const float*)d_in[12];
    const float* b1       = (const float*)d_in[13];
    const float* W2       = (const float*)d_in[14];
    const float* b2       = (const float*)d_in[15];
    float* out = (float*)d_out;

    void *pProtR, *pW1R, *pW2R, *pWoutR;
    void *pWh, *pS1, *pS2, *pAtt1, *pMulti, *pWh2, *pT1, *pT2, *pAtt2, *pHp2, *pHid;
    cudaGetSymbolAddress(&pProtR, g_protR);
    cudaGetSymbolAddress(&pW1R,  g_W1R);
    cudaGetSymbolAddress(&pW2R,  g_W2R);
    cudaGetSymbolAddress(&pWoutR,g_WoutR);
    cudaGetSymbolAddress(&pWh,   g_Wh);
    cudaGetSymbolAddress(&pS1,   g_s1);
    cudaGetSymbolAddress(&pS2,   g_s2);
    cudaGetSymbolAddress(&pAtt1, g_att1);
    cudaGetSymbolAddress(&pMulti,g_multi);
    cudaGetSymbolAddress(&pWh2,  g_Wh2);
    cudaGetSymbolAddress(&pT1,   g_t1);
    cudaGetSymbolAddress(&pT2,   g_t2);
    cudaGetSymbolAddress(&pAtt2, g_att2);
    cudaGetSymbolAddress(&pHp2,  g_hp2);
    cudaGetSymbolAddress(&pHid,  g_hid);

    static cudaStream_t sB = nullptr, sC = nullptr, sD = nullptr;
    static cudaEvent_t evFork = nullptr, evJoin = nullptr;
    static cudaEvent_t e0 = nullptr, e1 = nullptr, eW1 = nullptr, eD = nullptr;
    if (!sB) {
        cudaStreamCreateWithFlags(&sB, cudaStreamNonBlocking);
        cudaStreamCreateWithFlags(&sC, cudaStreamNonBlocking);
        cudaStreamCreateWithFlags(&sD, cudaStreamNonBlocking);
        cudaEventCreateWithFlags(&evFork, cudaEventDisableTiming);
        cudaEventCreateWithFlags(&evJoin, cudaEventDisableTiming);
        cudaEventCreateWithFlags(&e0, cudaEventDisableTiming);
        cudaEventCreateWithFlags(&e1, cudaEventDisableTiming);
        cudaEventCreateWithFlags(&eW1, cudaEventDisableTiming);
        cudaEventCreateWithFlags(&eD, cudaEventDisableTiming);
        cudaFuncSetAttribute(tf32gemm<128,128,16,64,64,1,4>,
                             cudaFuncAttributeMaxDynamicSharedMemorySize,
                             gemm_smem(128,128,16,4));
        cudaFuncSetAttribute(tf32gemm<32,128,16,16,32,2,3>,
                             cudaFuncAttributeMaxDynamicSharedMemorySize,
                             gemm_smem(32,128,16,3));
        cudaFuncSetAttribute(tf32gemm<128,64,16,64,16,3,3>,
                             cudaFuncAttributeMaxDynamicSharedMemorySize,
                             gemm_smem(128,64,16,3));
        cudaFuncSetAttribute(tf32gemm<64,128,16,32,32,4,3>,
                             cudaFuncAttributeMaxDynamicSharedMemorySize,
                             gemm_smem(64,128,16,3));
        cudaFuncSetAttribute(tf32gemm<64,128,16,32,32,0,3>,
                             cudaFuncAttributeMaxDynamicSharedMemorySize,
                             gemm_smem(64,128,16,3));
    }

    const long PROT_HALF = 16L * 1024 * 1152 / 2;    // elements per half

    // ---- fork ----
    cudaEventRecord(evFork, 0);
    cudaStreamWaitEvent(sB, evFork, 0);
    cudaStreamWaitEvent(sC, evFork, 0);
    cudaStreamWaitEvent(sD, evFork, 0);

    // stream B: prot rounding in two halves
    k_round<<<1024, 256, 0, sB>>>(prot, (float*)pProtR, (int)(PROT_HALF / 4));
    cudaEventRecord(e0, sB);
    k_round<<<1024, 256, 0, sB>>>(prot + PROT_HALF, (float*)pProtR + PROT_HALF,
                                  (int)(PROT_HALF / 4));
    cudaEventRecord(e1, sB);

    // stream C: W1 round, FC1 half0, then FC2 (after half1 on sD finishes)
    k_round<<<148, 256, 0, sC>>>(W1, (float*)pW1R, 1152 * 512 / 4);
    cudaEventRecord(eW1, sC);
    cudaStreamWaitEvent(sC, e0, 0);
    tf32gemm<128,128,16,64,64,1,4><<<dim3(4,64,1), 128, gemm_smem(128,128,16,4), sC>>>(
        (const float*)pProtR, (const float*)pW1R, b1, (float*)pHid,
        16384, 512, 1152, 0, 0);

    // stream D: FC1 half1 runs CONCURRENTLY with half0
    cudaStreamWaitEvent(sD, eW1, 0);
    cudaStreamWaitEvent(sD, e1, 0);
    tf32gemm<128,128,16,64,64,1,4><<<dim3(4,64,1), 128, gemm_smem(128,128,16,4), sD>>>(
        (const float*)pProtR + PROT_HALF, (const float*)pW1R, b1,
        (float*)pHid + 8192L * 512, 16384, 512, 1152, 0, 0);
    cudaEventRecord(eD, sD);

    // stream C continues: W2 round + FC2 (needs both halves of hid)
    k_round<<<32, 256, 0, sC>>>(W2, (float*)pW2R, 512 * 128 / 4);
    cudaStreamWaitEvent(sC, eD, 0);
    tf32gemm<32,128,16,16,32,2,3><<<dim3(1,512,1), 256, gemm_smem(32,128,16,3), sC>>>(
        (const float*)pHid, (const float*)pW2R, b2, out, 16384, 128, 512, 0, 0);
    cudaEventRecord(evJoin, sC);

    // ---- GAT chain on origin stream ----
    k_embed_gat1<<<16 * 512, 256>>>(atoms, emb_atom, W_gat, a_gat);
    k_round<<<16, 256>>>(W_out, (float*)pWoutR, 256 * 128 / 4);
    k_att_rows4<<<16 * 512, 256>>>((const float*)pS1, (const float*)pS2,
                                   adj, (float*)pAtt1);
    // multi = elu(att1 @ Wh)   [512 x 64 x 512] x 64 batches
    tf32gemm<128,64,16,64,16,3,3><<<dim3(1,4,64), 256, gemm_smem(128,64,16,3)>>>(
        (const float*)pAtt1, (const float*)pWh, nullptr, (float*)pMulti,
        512, 64, 512, (long)512 * 512, (long)512 * 64);
    // Wh2 = multi @ W_out   [8192 x 128 x 256]
    tf32gemm<64,128,16,32,32,4,3><<<dim3(1,128,1), 256, gemm_smem(64,128,16,3)>>>(
        (const float*)pMulti, (const float*)pWoutR, nullptr, (float*)pWh2,
        8192, 128, 256, 0, 0);
    k_t12<<<16 * 512, 128>>>(a_out);
    k_att_rows1<<<16 * 512, 256>>>((const float*)pT1, (const float*)pT2,
                                   adj, (float*)pAtt2);
    // hp2 = att2 @ Wh2   [512 x 128 x 512] x 16 batches
    tf32gemm<64,128,16,32,32,0,3><<<dim3(1,8,16), 256, gemm_smem(64,128,16,3)>>>(
        (const float*)pAtt2, (const float*)pWh2, nullptr, (float*)pHp2,
        512, 128, 512, (long)512 * 512, (long)512 * 128);
    k_final_atoms<<<16 * 512, 128>>>(Wc, bc, out);

    // ---- join ----
    cudaStreamWaitEvent(0, evJoin, 0);
}